// round 2
// baseline (speedup 1.0000x reference)
#include <cuda_runtime.h>
#include <math.h>

#define TT   2048
#define DD   768
#define HH   12
#define DKK  64
#define FFD  2048
#define LL   12
#define VV   50304
#define KC   4
#define EPSF 1e-6f

// ---------------- scratch (static device globals; no allocation) ----------------
__device__ float g_h   [TT*DD];
__device__ float g_x   [TT*DD];
__device__ float g_q   [TT*DD];
__device__ float g_k   [TT*DD];
__device__ float g_v   [TT*DD];
__device__ float g_qc  [TT*DD];
__device__ float g_kc  [TT*DD];
__device__ float g_vc  [TT*DD];
__device__ float g_o   [TT*DD];
__device__ float g_beta[TT*HH];
__device__ float g_gate[TT*FFD];
__device__ float g_up  [TT*FFD];
__device__ float g_rowloss[TT];

// ---------------- kernels ----------------

__global__ void embed_k(const int* __restrict__ idx, const float* __restrict__ emb,
                        float* __restrict__ h) {
    int i = blockIdx.x * 256 + threadIdx.x;
    if (i < TT * DD) {
        int t = i / DD, d = i - t * DD;
        h[i] = emb[(size_t)idx[t] * DD + d];
    }
}

// RMSNorm over D=768 per row (mean-square version, with weight)
__global__ void rmsnorm_k(const float* __restrict__ in, const float* __restrict__ w,
                          float* __restrict__ out) {
    int t = blockIdx.x;
    const float* row = in + (size_t)t * DD;
    __shared__ float red[256];
    float s = 0.f;
    for (int i = threadIdx.x; i < DD; i += 256) { float v = row[i]; s += v * v; }
    red[threadIdx.x] = s; __syncthreads();
    for (int off = 128; off > 0; off >>= 1) {
        if (threadIdx.x < off) red[threadIdx.x] += red[threadIdx.x + off];
        __syncthreads();
    }
    float scale = rsqrtf(red[0] / (float)DD + EPSF);
    for (int i = threadIdx.x; i < DD; i += 256)
        out[(size_t)t * DD + i] = row[i] * scale * w[i];
}

// Tiled fp32 GEMM: C[M,N] (+)= A[M,K] @ B[K,N]; all M%64==0, N%64==0, K%16==0.
template <bool ACC>
__global__ void gemm_k(const float* __restrict__ A, const float* __restrict__ B,
                       float* __restrict__ C, int M, int N, int Kd) {
    __shared__ float As[16][64];
    __shared__ float Bs[16][64];
    const int bn = blockIdx.x * 64, bm = blockIdx.y * 64;
    const int tid = threadIdx.x;
    const int tx = tid & 15, ty = tid >> 4;
    const int ar = tid >> 2, ac = (tid & 3) * 4;
    const int br = tid >> 4, bc = (tid & 15) * 4;
    float acc[4][4];
#pragma unroll
    for (int i = 0; i < 4; i++)
#pragma unroll
        for (int j = 0; j < 4; j++) acc[i][j] = 0.f;

    for (int k0 = 0; k0 < Kd; k0 += 16) {
        float4 a4 = *(const float4*)(A + (size_t)(bm + ar) * Kd + k0 + ac);
        As[ac + 0][ar] = a4.x; As[ac + 1][ar] = a4.y;
        As[ac + 2][ar] = a4.z; As[ac + 3][ar] = a4.w;
        *(float4*)&Bs[br][bc] = *(const float4*)(B + (size_t)(k0 + br) * N + bn + bc);
        __syncthreads();
#pragma unroll
        for (int kk = 0; kk < 16; kk++) {
            float4 a = *(const float4*)&As[kk][ty * 4];
            float4 b = *(const float4*)&Bs[kk][tx * 4];
            acc[0][0] += a.x * b.x; acc[0][1] += a.x * b.y; acc[0][2] += a.x * b.z; acc[0][3] += a.x * b.w;
            acc[1][0] += a.y * b.x; acc[1][1] += a.y * b.y; acc[1][2] += a.y * b.z; acc[1][3] += a.y * b.w;
            acc[2][0] += a.z * b.x; acc[2][1] += a.z * b.y; acc[2][2] += a.z * b.z; acc[2][3] += a.z * b.w;
            acc[3][0] += a.w * b.x; acc[3][1] += a.w * b.y; acc[3][2] += a.w * b.z; acc[3][3] += a.w * b.w;
        }
        __syncthreads();
    }
#pragma unroll
    for (int i = 0; i < 4; i++) {
        float* cp = C + (size_t)(bm + ty * 4 + i) * N + bn + tx * 4;
        if (ACC) {
            float4 c = *(float4*)cp;
            c.x += acc[i][0]; c.y += acc[i][1]; c.z += acc[i][2]; c.w += acc[i][3];
            *(float4*)cp = c;
        } else {
            *(float4*)cp = make_float4(acc[i][0], acc[i][1], acc[i][2], acc[i][3]);
        }
    }
}

// beta = sigmoid(x @ Wb), Wb: [D,H]; one thread per (t,h)
__global__ void beta_k(const float* __restrict__ x, const float* __restrict__ Wb,
                       float* __restrict__ beta) {
    int g = blockIdx.x * blockDim.x + threadIdx.x;
    if (g >= TT * HH) return;
    int t = g / HH, h = g - t * HH;
    const float* xr = x + (size_t)t * DD;
    float s = 0.f;
    for (int i = 0; i < DD; i++) s += xr[i] * Wb[i * HH + h];
    beta[g] = 1.f / (1.f + expf(-s));
}

// causal depthwise conv (K=4) + SiLU, per (t,d)
__global__ void conv_silu_k(const float* __restrict__ x, const float* __restrict__ w,
                            float* __restrict__ y) {
    int i = blockIdx.x * 256 + threadIdx.x;
    if (i >= TT * DD) return;
    int t = i / DD, d = i - t * DD;
    float acc = 0.f;
#pragma unroll
    for (int j = 0; j < KC; j++) {
        int tt = t - (KC - 1) + j;
        if (tt >= 0) acc += x[(size_t)tt * DD + d] * w[d * KC + j];
    }
    y[i] = acc / (1.f + expf(-acc));
}

// l2norm over dk=64 per (t,h), in place (sum, not mean)
__global__ void l2norm_k(float* __restrict__ x) {
    int g = blockIdx.x * blockDim.x + threadIdx.x;
    if (g >= TT * HH) return;
    int t = g / HH, h = g - t * HH;
    float* p = x + (size_t)t * DD + h * DKK;
    float s = 0.f;
#pragma unroll
    for (int i = 0; i < DKK; i++) s += p[i] * p[i];
    float sc = rsqrtf(s + EPSF);
#pragma unroll
    for (int i = 0; i < DKK; i++) p[i] *= sc;
}

// per-head RMSNorm (mean) with weight w[64], in place
__global__ void headnorm_k(float* __restrict__ o, const float* __restrict__ w) {
    int g = blockIdx.x * blockDim.x + threadIdx.x;
    if (g >= TT * HH) return;
    int t = g / HH, h = g - t * HH;
    float* p = o + (size_t)t * DD + h * DKK;
    float s = 0.f;
#pragma unroll
    for (int i = 0; i < DKK; i++) s += p[i] * p[i];
    float sc = rsqrtf(s / (float)DKK + EPSF);
#pragma unroll
    for (int i = 0; i < DKK; i++) p[i] = p[i] * sc * w[i];
}

// delta-rule recurrence: one block per head, 64 threads; thread j owns S[:,j]
__global__ void delta_k(const float* __restrict__ q, const float* __restrict__ k,
                        const float* __restrict__ v, const float* __restrict__ beta,
                        float* __restrict__ o) {
    const int h = blockIdx.x;
    const int j = threadIdx.x;
    float S[DKK];
#pragma unroll
    for (int i = 0; i < DKK; i++) S[i] = 0.f;
    __shared__ float qs[DKK], ks[DKK], vs[DKK];
    __shared__ float bsh;
    for (int t = 0; t < TT; t++) {
        const int base = t * DD + h * DKK;
        qs[j] = q[base + j];
        ks[j] = k[base + j];
        vs[j] = v[base + j];
        if (j == 0) bsh = beta[t * HH + h];
        __syncthreads();
        float a0 = 0.f, a1 = 0.f, a2 = 0.f, a3 = 0.f;
#pragma unroll
        for (int i = 0; i < DKK; i += 4) {
            a0 += ks[i + 0] * S[i + 0];
            a1 += ks[i + 1] * S[i + 1];
            a2 += ks[i + 2] * S[i + 2];
            a3 += ks[i + 3] * S[i + 3];
        }
        float w = bsh * (vs[j] - ((a0 + a1) + (a2 + a3)));
        float o0 = 0.f, o1 = 0.f, o2 = 0.f, o3 = 0.f;
#pragma unroll
        for (int i = 0; i < DKK; i += 4) {
            S[i + 0] += ks[i + 0] * w; o0 += qs[i + 0] * S[i + 0];
            S[i + 1] += ks[i + 1] * w; o1 += qs[i + 1] * S[i + 1];
            S[i + 2] += ks[i + 2] * w; o2 += qs[i + 2] * S[i + 2];
            S[i + 3] += ks[i + 3] * w; o3 += qs[i + 3] * S[i + 3];
        }
        o[base + j] = (o0 + o1) + (o2 + o3);
        __syncthreads();
    }
}

// g = silu(g) * u, elementwise
__global__ void silu_mul_k(float* __restrict__ g, const float* __restrict__ u) {
    int i = blockIdx.x * 256 + threadIdx.x;
    if (i < TT * FFD) {
        float x = g[i];
        g[i] = (x / (1.f + expf(-x))) * u[i];
    }
}

// per-row NLL: rowloss[t] = logsumexp(logits[t,:]) - logits[t, tgt[t]]
__global__ void loss_rows_k(const float* __restrict__ logits, const int* __restrict__ tgt,
                            float* __restrict__ rowloss) {
    int t = blockIdx.x;
    const float* row = logits + (size_t)t * VV;
    __shared__ float red[256];
    float m = -1e30f;
    for (int i = threadIdx.x; i < VV; i += 256) m = fmaxf(m, row[i]);
    red[threadIdx.x] = m; __syncthreads();
    for (int off = 128; off > 0; off >>= 1) {
        if (threadIdx.x < off) red[threadIdx.x] = fmaxf(red[threadIdx.x], red[threadIdx.x + off]);
        __syncthreads();
    }
    m = red[0]; __syncthreads();
    float s = 0.f;
    for (int i = threadIdx.x; i < VV; i += 256) s += expf(row[i] - m);
    red[threadIdx.x] = s; __syncthreads();
    for (int off = 128; off > 0; off >>= 1) {
        if (threadIdx.x < off) red[threadIdx.x] += red[threadIdx.x + off];
        __syncthreads();
    }
    if (threadIdx.x == 0) {
        int tg = tgt[t];
        if (tg < 0) tg = 0;
        if (tg > VV - 1) tg = VV - 1;
        rowloss[t] = (m + logf(red[0])) - row[tg];
    }
}

__global__ void loss_final_k(const float* __restrict__ rowloss, float* __restrict__ out) {
    __shared__ float red[256];
    float s = 0.f;
    for (int i = threadIdx.x; i < TT; i += 256) s += rowloss[i];
    red[threadIdx.x] = s; __syncthreads();
    for (int off = 128; off > 0; off >>= 1) {
        if (threadIdx.x < off) red[threadIdx.x] += red[threadIdx.x + off];
        __syncthreads();
    }
    if (threadIdx.x == 0) out[0] = red[0] / (float)TT;
}

// ---------------- host launch ----------------

extern "C" void kernel_launch(void* const* d_in, const int* in_sizes, int n_in,
                              void* d_out, int out_size) {
    const int*   idx          = (const int*)d_in[0];
    const int*   targets      = (const int*)d_in[1];
    const float* embed        = (const float*)d_in[2];
    const float* Wq           = (const float*)d_in[3];
    const float* Wk           = (const float*)d_in[4];
    const float* Wv           = (const float*)d_in[5];
    const float* conv_q       = (const float*)d_in[6];
    const float* conv_k       = (const float*)d_in[7];
    const float* conv_v       = (const float*)d_in[8];
    const float* Wb           = (const float*)d_in[9];
    const float* o_norm_w     = (const float*)d_in[10];
    const float* Wo           = (const float*)d_in[11];
    const float* attn_norm_w  = (const float*)d_in[12];
    const float* mlp_norm_w   = (const float*)d_in[13];
    const float* Wgate        = (const float*)d_in[14];
    const float* Wup          = (const float*)d_in[15];
    const float* Wdown        = (const float*)d_in[16];
    const float* final_norm_w = (const float*)d_in[17];
    const float* lm_head      = (const float*)d_in[18];
    float* out = (float*)d_out;

    float *h, *x, *q, *k, *v, *qc, *kc, *vc, *o, *bet, *gate, *up, *rowloss;
    cudaGetSymbolAddress((void**)&h,   g_h);
    cudaGetSymbolAddress((void**)&x,   g_x);
    cudaGetSymbolAddress((void**)&q,   g_q);
    cudaGetSymbolAddress((void**)&k,   g_k);
    cudaGetSymbolAddress((void**)&v,   g_v);
    cudaGetSymbolAddress((void**)&qc,  g_qc);
    cudaGetSymbolAddress((void**)&kc,  g_kc);
    cudaGetSymbolAddress((void**)&vc,  g_vc);
    cudaGetSymbolAddress((void**)&o,   g_o);
    cudaGetSymbolAddress((void**)&bet, g_beta);
    cudaGetSymbolAddress((void**)&gate,g_gate);
    cudaGetSymbolAddress((void**)&up,  g_up);
    cudaGetSymbolAddress((void**)&rowloss, g_rowloss);

    const int eltTD = (TT * DD + 255) / 256;
    const int eltTH = (TT * HH + 255) / 256;
    const int eltTF = (TT * FFD + 255) / 256;

    embed_k<<<eltTD, 256>>>(idx, embed, h);

    dim3 g768(DD / 64, TT / 64);
    dim3 gff (FFD / 64, TT / 64);

    for (int l = 0; l < LL; l++) {
        rmsnorm_k<<<TT, 256>>>(h, attn_norm_w + (size_t)l * DD, x);

        gemm_k<false><<<g768, 256>>>(x, Wq + (size_t)l * DD * DD, q, TT, DD, DD);
        gemm_k<false><<<g768, 256>>>(x, Wk + (size_t)l * DD * DD, k, TT, DD, DD);
        gemm_k<false><<<g768, 256>>>(x, Wv + (size_t)l * DD * DD, v, TT, DD, DD);
        beta_k<<<eltTH, 256>>>(x, Wb + (size_t)l * DD * HH, bet);

        conv_silu_k<<<eltTD, 256>>>(q, conv_q + (size_t)l * DD * KC, qc);
        conv_silu_k<<<eltTD, 256>>>(k, conv_k + (size_t)l * DD * KC, kc);
        conv_silu_k<<<eltTD, 256>>>(v, conv_v + (size_t)l * DD * KC, vc);

        l2norm_k<<<eltTH, 256>>>(qc);
        l2norm_k<<<eltTH, 256>>>(kc);

        delta_k<<<HH, DKK>>>(qc, kc, vc, bet, o);
        headnorm_k<<<eltTH, 256>>>(o, o_norm_w + (size_t)l * DKK);

        gemm_k<true><<<g768, 256>>>(o, Wo + (size_t)l * DD * DD, h, TT, DD, DD);

        rmsnorm_k<<<TT, 256>>>(h, mlp_norm_w + (size_t)l * DD, x);
        gemm_k<false><<<gff, 256>>>(x, Wgate + (size_t)l * DD * FFD, gate, TT, FFD, DD);
        gemm_k<false><<<gff, 256>>>(x, Wup   + (size_t)l * DD * FFD, up,   TT, FFD, DD);
        silu_mul_k<<<eltTF, 256>>>(gate, up);
        gemm_k<true><<<g768, 256>>>(gate, Wdown + (size_t)l * FFD * DD, h, TT, DD, FFD);
    }

    rmsnorm_k<<<TT, 256>>>(h, final_norm_w, x);

    if ((long long)out_size >= (long long)TT * VV) {
        dim3 gv(VV / 64, TT / 64);
        gemm_k<false><<<gv, 256>>>(x, lm_head, out, TT, VV, DD);
        loss_rows_k<<<TT, 256>>>(out, targets, rowloss);
        if ((long long)out_size > (long long)TT * VV)
            loss_final_k<<<1, 256>>>(rowloss, out + (size_t)TT * VV);
    }
}

// round 4
// speedup vs baseline: 1.7513x; 1.7513x over previous
#include <cuda_runtime.h>
#include <cuda_bf16.h>
#include <mma.h>
#include <math.h>

using namespace nvcuda;

#define TT   2048
#define DD   768
#define HH   12
#define DKK  64
#define FFD  2048
#define LL   12
#define VV   50304
#define KC   4
#define EPSF 1e-6f

// ---------------- scratch (static device globals; no allocation) ----------------
__device__ float g_h   [TT*DD];
__device__ float g_x   [TT*DD];
__device__ float g_q   [TT*DD];
__device__ float g_k   [TT*DD];
__device__ float g_v   [TT*DD];
__device__ float g_qc  [TT*DD];
__device__ float g_kc  [TT*DD];
__device__ float g_vc  [TT*DD];
__device__ float g_o   [TT*DD];
__device__ float g_beta[TT*HH];
__device__ float g_gate[TT*FFD];
__device__ float g_up  [TT*FFD];
__device__ float g_rowloss[TT];

// ---------------- small kernels ----------------

__global__ void embed_k(const int* __restrict__ idx, const float* __restrict__ emb,
                        float* __restrict__ h) {
    int i = blockIdx.x * 256 + threadIdx.x;
    if (i < TT * DD) {
        int t = i / DD, d = i - t * DD;
        h[i] = emb[(size_t)idx[t] * DD + d];
    }
}

__global__ void rmsnorm_k(const float* __restrict__ in, const float* __restrict__ w,
                          float* __restrict__ out) {
    int t = blockIdx.x;
    const float* row = in + (size_t)t * DD;
    __shared__ float red[256];
    float s = 0.f;
    for (int i = threadIdx.x; i < DD; i += 256) { float v = row[i]; s += v * v; }
    red[threadIdx.x] = s; __syncthreads();
    for (int off = 128; off > 0; off >>= 1) {
        if (threadIdx.x < off) red[threadIdx.x] += red[threadIdx.x + off];
        __syncthreads();
    }
    float scale = rsqrtf(red[0] / (float)DD + EPSF);
    for (int i = threadIdx.x; i < DD; i += 256)
        out[(size_t)t * DD + i] = row[i] * scale * w[i];
}

// ---------------- bf16 split-precision (3-MMA) tensor-core GEMM ----------------
// C[M,N] (+)= A[M,K] @ B[K,N]  with  A ~ Ahi+Alo, B ~ Bhi+Blo (bf16 pairs),
// C = Ahi*Bhi + Alo*Bhi + Ahi*Blo  (fp32 accum).  BM=128 BN=128 BK=32, 8 warps.
// blockIdx.z selects among up to 3 (B,C) pairs sharing the same A.
#define LDA 56    // bf16 elems per A row (32 used); 112B stride, conflict-free ldmatrix
#define LDB 136   // bf16 elems per B row (128 used); 272B stride

template <bool ACC>
__global__ __launch_bounds__(256) void gemm_tc(
    const float* __restrict__ A,
    const float* __restrict__ B0, const float* __restrict__ B1, const float* __restrict__ B2,
    float* __restrict__ C0, float* __restrict__ C1, float* __restrict__ C2,
    int M, int N, int K) {
    const float* B = (blockIdx.z == 0) ? B0 : (blockIdx.z == 1) ? B1 : B2;
    float*       C = (blockIdx.z == 0) ? C0 : (blockIdx.z == 1) ? C1 : C2;

    __shared__ __nv_bfloat16 As[2][128 * LDA];  // [hi|lo]
    __shared__ __nv_bfloat16 Bs[2][32 * LDB];

    const int bm = blockIdx.y * 128;
    const int bn = blockIdx.x * 128;
    const int tid = threadIdx.x;
    const int warp = tid >> 5;
    const int wm = warp >> 2;        // 0..1 -> 64-row slab
    const int wn = warp & 3;         // 0..3 -> 32-col slab

    const int lrow = tid >> 3;       // 0..31
    const int lc4  = (tid & 7) * 4;  // 0,4,...,28

    wmma::fragment<wmma::accumulator, 16, 16, 16, float> acc[4][2];
#pragma unroll
    for (int mi = 0; mi < 4; mi++)
#pragma unroll
        for (int ni = 0; ni < 2; ni++) wmma::fill_fragment(acc[mi][ni], 0.f);

    for (int k0 = 0; k0 < K; k0 += 32) {
        // A tile: 128x32, split into hi/lo bf16
#pragma unroll
        for (int r = 0; r < 4; r++) {
            int row = lrow + r * 32;
            float4 v = *(const float4*)(A + (size_t)(bm + row) * K + k0 + lc4);
            __nv_bfloat16 hx = __float2bfloat16(v.x), hy = __float2bfloat16(v.y);
            __nv_bfloat16 hz = __float2bfloat16(v.z), hw = __float2bfloat16(v.w);
            __nv_bfloat16* ph = &As[0][row * LDA + lc4];
            __nv_bfloat16* pl = &As[1][row * LDA + lc4];
            ph[0] = hx; ph[1] = hy; ph[2] = hz; ph[3] = hw;
            pl[0] = __float2bfloat16(v.x - __bfloat162float(hx));
            pl[1] = __float2bfloat16(v.y - __bfloat162float(hy));
            pl[2] = __float2bfloat16(v.z - __bfloat162float(hz));
            pl[3] = __float2bfloat16(v.w - __bfloat162float(hw));
        }
        // B tile: 32x128, split into hi/lo bf16
#pragma unroll
        for (int c = 0; c < 4; c++) {
            int col = lc4 + c * 32;
            float4 v = *(const float4*)(B + (size_t)(k0 + lrow) * N + bn + col);
            __nv_bfloat16 hx = __float2bfloat16(v.x), hy = __float2bfloat16(v.y);
            __nv_bfloat16 hz = __float2bfloat16(v.z), hw = __float2bfloat16(v.w);
            __nv_bfloat16* ph = &Bs[0][lrow * LDB + col];
            __nv_bfloat16* pl = &Bs[1][lrow * LDB + col];
            ph[0] = hx; ph[1] = hy; ph[2] = hz; ph[3] = hw;
            pl[0] = __float2bfloat16(v.x - __bfloat162float(hx));
            pl[1] = __float2bfloat16(v.y - __bfloat162float(hy));
            pl[2] = __float2bfloat16(v.z - __bfloat162float(hz));
            pl[3] = __float2bfloat16(v.w - __bfloat162float(hw));
        }
        __syncthreads();

#pragma unroll
        for (int kk = 0; kk < 32; kk += 16) {
            wmma::fragment<wmma::matrix_a, 16, 16, 16, __nv_bfloat16, wmma::row_major> ah[4], al[4];
#pragma unroll
            for (int mi = 0; mi < 4; mi++) {
                wmma::load_matrix_sync(ah[mi], &As[0][(wm * 64 + mi * 16) * LDA + kk], LDA);
                wmma::load_matrix_sync(al[mi], &As[1][(wm * 64 + mi * 16) * LDA + kk], LDA);
            }
#pragma unroll
            for (int ni = 0; ni < 2; ni++) {
                wmma::fragment<wmma::matrix_b, 16, 16, 16, __nv_bfloat16, wmma::row_major> bh, bl;
                wmma::load_matrix_sync(bh, &Bs[0][kk * LDB + wn * 32 + ni * 16], LDB);
                wmma::load_matrix_sync(bl, &Bs[1][kk * LDB + wn * 32 + ni * 16], LDB);
#pragma unroll
                for (int mi = 0; mi < 4; mi++) {
                    wmma::mma_sync(acc[mi][ni], ah[mi], bh, acc[mi][ni]);
                    wmma::mma_sync(acc[mi][ni], al[mi], bh, acc[mi][ni]);
                    wmma::mma_sync(acc[mi][ni], ah[mi], bl, acc[mi][ni]);
                }
            }
        }
        __syncthreads();
    }

#pragma unroll
    for (int mi = 0; mi < 4; mi++)
#pragma unroll
        for (int ni = 0; ni < 2; ni++) {
            float* cp = C + (size_t)(bm + wm * 64 + mi * 16) * N + bn + wn * 32 + ni * 16;
            if (ACC) {
                wmma::fragment<wmma::accumulator, 16, 16, 16, float> cf;
                wmma::load_matrix_sync(cf, cp, N, wmma::mem_row_major);
#pragma unroll
                for (int e = 0; e < cf.num_elements; e++) acc[mi][ni].x[e] += cf.x[e];
            }
            wmma::store_matrix_sync(cp, acc[mi][ni], N, wmma::mem_row_major);
        }
}

// beta = sigmoid(x @ Wb), Wb: [D,H]
__global__ void beta_k(const float* __restrict__ x, const float* __restrict__ Wb,
                       float* __restrict__ beta) {
    int g = blockIdx.x * blockDim.x + threadIdx.x;
    if (g >= TT * HH) return;
    int t = g / HH, h = g - t * HH;
    const float* xr = x + (size_t)t * DD;
    float s = 0.f;
    for (int i = 0; i < DD; i++) s += xr[i] * Wb[i * HH + h];
    beta[g] = 1.f / (1.f + expf(-s));
}

__global__ void conv_silu_k(const float* __restrict__ x, const float* __restrict__ w,
                            float* __restrict__ y) {
    int i = blockIdx.x * 256 + threadIdx.x;
    if (i >= TT * DD) return;
    int t = i / DD, d = i - t * DD;
    float acc = 0.f;
#pragma unroll
    for (int j = 0; j < KC; j++) {
        int tt = t - (KC - 1) + j;
        if (tt >= 0) acc += x[(size_t)tt * DD + d] * w[d * KC + j];
    }
    y[i] = acc / (1.f + expf(-acc));
}

__global__ void l2norm_k(float* __restrict__ x) {
    int g = blockIdx.x * blockDim.x + threadIdx.x;
    if (g >= TT * HH) return;
    int t = g / HH, h = g - t * HH;
    float* p = x + (size_t)t * DD + h * DKK;
    float s = 0.f;
#pragma unroll
    for (int i = 0; i < DKK; i++) s += p[i] * p[i];
    float sc = rsqrtf(s + EPSF);
#pragma unroll
    for (int i = 0; i < DKK; i++) p[i] *= sc;
}

__global__ void headnorm_k(float* __restrict__ o, const float* __restrict__ w) {
    int g = blockIdx.x * blockDim.x + threadIdx.x;
    if (g >= TT * HH) return;
    int t = g / HH, h = g - t * HH;
    float* p = o + (size_t)t * DD + h * DKK;
    float s = 0.f;
#pragma unroll
    for (int i = 0; i < DKK; i++) s += p[i] * p[i];
    float sc = rsqrtf(s / (float)DKK + EPSF);
#pragma unroll
    for (int i = 0; i < DKK; i++) p[i] = p[i] * sc * w[i];
}

// delta-rule recurrence with register prefetch of the next step's inputs
__global__ void delta_k(const float* __restrict__ q, const float* __restrict__ k,
                        const float* __restrict__ v, const float* __restrict__ beta,
                        float* __restrict__ o) {
    const int h = blockIdx.x;
    const int j = threadIdx.x;
    float S[DKK];
#pragma unroll
    for (int i = 0; i < DKK; i++) S[i] = 0.f;
    __shared__ float qs[DKK], ks[DKK], vs[DKK];
    __shared__ float bsh;

    int base = h * DKK + j;
    float qn = q[base], kn = k[base], vn = v[base];
    float bn_ = beta[h];

    for (int t = 0; t < TT; t++) {
        qs[j] = qn; ks[j] = kn; vs[j] = vn;
        if (j == 0) bsh = bn_;
        __syncthreads();
        if (t + 1 < TT) {
            int nb = (t + 1) * DD + h * DKK + j;
            qn = q[nb]; kn = k[nb]; vn = v[nb];
            bn_ = beta[(t + 1) * HH + h];
        }
        float a0 = 0.f, a1 = 0.f, a2 = 0.f, a3 = 0.f;
#pragma unroll
        for (int i = 0; i < DKK; i += 4) {
            a0 += ks[i + 0] * S[i + 0];
            a1 += ks[i + 1] * S[i + 1];
            a2 += ks[i + 2] * S[i + 2];
            a3 += ks[i + 3] * S[i + 3];
        }
        float w = bsh * (vs[j] - ((a0 + a1) + (a2 + a3)));
        float o0 = 0.f, o1 = 0.f, o2 = 0.f, o3 = 0.f;
#pragma unroll
        for (int i = 0; i < DKK; i += 4) {
            S[i + 0] += ks[i + 0] * w; o0 += qs[i + 0] * S[i + 0];
            S[i + 1] += ks[i + 1] * w; o1 += qs[i + 1] * S[i + 1];
            S[i + 2] += ks[i + 2] * w; o2 += qs[i + 2] * S[i + 2];
            S[i + 3] += ks[i + 3] * w; o3 += qs[i + 3] * S[i + 3];
        }
        o[t * DD + h * DKK + j] = (o0 + o1) + (o2 + o3);
        __syncthreads();
    }
}

__global__ void silu_mul_k(float* __restrict__ g, const float* __restrict__ u) {
    int i = blockIdx.x * 256 + threadIdx.x;
    if (i < TT * FFD) {
        float x = g[i];
        g[i] = (x / (1.f + expf(-x))) * u[i];
    }
}

__global__ void loss_rows_k(const float* __restrict__ logits, const int* __restrict__ tgt,
                            float* __restrict__ rowloss) {
    int t = blockIdx.x;
    const float* row = logits + (size_t)t * VV;
    __shared__ float red[256];
    float m = -1e30f;
    for (int i = threadIdx.x; i < VV; i += 256) m = fmaxf(m, row[i]);
    red[threadIdx.x] = m; __syncthreads();
    for (int off = 128; off > 0; off >>= 1) {
        if (threadIdx.x < off) red[threadIdx.x] = fmaxf(red[threadIdx.x], red[threadIdx.x + off]);
        __syncthreads();
    }
    m = red[0]; __syncthreads();
    float s = 0.f;
    for (int i = threadIdx.x; i < VV; i += 256) s += expf(row[i] - m);
    red[threadIdx.x] = s; __syncthreads();
    for (int off = 128; off > 0; off >>= 1) {
        if (threadIdx.x < off) red[threadIdx.x] += red[threadIdx.x + off];
        __syncthreads();
    }
    if (threadIdx.x == 0) {
        int tg = tgt[t];
        if (tg < 0) tg = 0;
        if (tg > VV - 1) tg = VV - 1;
        rowloss[t] = (m + logf(red[0])) - row[tg];
    }
}

__global__ void loss_final_k(const float* __restrict__ rowloss, float* __restrict__ out) {
    __shared__ float red[256];
    float s = 0.f;
    for (int i = threadIdx.x; i < TT; i += 256) s += rowloss[i];
    red[threadIdx.x] = s; __syncthreads();
    for (int off = 128; off > 0; off >>= 1) {
        if (threadIdx.x < off) red[threadIdx.x] += red[threadIdx.x + off];
        __syncthreads();
    }
    if (threadIdx.x == 0) out[0] = red[0] / (float)TT;
}

// ---------------- host launch ----------------

extern "C" void kernel_launch(void* const* d_in, const int* in_sizes, int n_in,
                              void* d_out, int out_size) {
    const int*   idx          = (const int*)d_in[0];
    const int*   targets      = (const int*)d_in[1];
    const float* embed        = (const float*)d_in[2];
    const float* Wq           = (const float*)d_in[3];
    const float* Wk           = (const float*)d_in[4];
    const float* Wv           = (const float*)d_in[5];
    const float* conv_q       = (const float*)d_in[6];
    const float* conv_k       = (const float*)d_in[7];
    const float* conv_v       = (const float*)d_in[8];
    const float* Wb           = (const float*)d_in[9];
    const float* o_norm_w     = (const float*)d_in[10];
    const float* Wo           = (const float*)d_in[11];
    const float* attn_norm_w  = (const float*)d_in[12];
    const float* mlp_norm_w   = (const float*)d_in[13];
    const float* Wgate        = (const float*)d_in[14];
    const float* Wup          = (const float*)d_in[15];
    const float* Wdown        = (const float*)d_in[16];
    const float* final_norm_w = (const float*)d_in[17];
    const float* lm_head      = (const float*)d_in[18];
    float* out = (float*)d_out;

    float *h, *x, *q, *k, *v, *qc, *kc, *vc, *o, *bet, *gate, *up, *rowloss;
    cudaGetSymbolAddress((void**)&h,   g_h);
    cudaGetSymbolAddress((void**)&x,   g_x);
    cudaGetSymbolAddress((void**)&q,   g_q);
    cudaGetSymbolAddress((void**)&k,   g_k);
    cudaGetSymbolAddress((void**)&v,   g_v);
    cudaGetSymbolAddress((void**)&qc,  g_qc);
    cudaGetSymbolAddress((void**)&kc,  g_kc);
    cudaGetSymbolAddress((void**)&vc,  g_vc);
    cudaGetSymbolAddress((void**)&o,   g_o);
    cudaGetSymbolAddress((void**)&bet, g_beta);
    cudaGetSymbolAddress((void**)&gate,g_gate);
    cudaGetSymbolAddress((void**)&up,  g_up);
    cudaGetSymbolAddress((void**)&rowloss, g_rowloss);

    const int eltTD = (TT * DD + 255) / 256;
    const int eltTH = (TT * HH + 255) / 256;
    const int eltTF = (TT * FFD + 255) / 256;

    embed_k<<<eltTD, 256>>>(idx, embed, h);

    dim3 g_qkv(DD / 128, TT / 128, 3);   // fused q,k,v
    dim3 g_one(DD / 128, TT / 128, 1);
    dim3 g_gu (FFD / 128, TT / 128, 2);  // fused gate,up
    dim3 g_vcb(VV / 128, TT / 128, 1);

    for (int l = 0; l < LL; l++) {
        rmsnorm_k<<<TT, 256>>>(h, attn_norm_w + (size_t)l * DD, x);

        gemm_tc<false><<<g_qkv, 256>>>(x,
            Wq + (size_t)l * DD * DD, Wk + (size_t)l * DD * DD, Wv + (size_t)l * DD * DD,
            q, k, v, TT, DD, DD);
        beta_k<<<eltTH, 256>>>(x, Wb + (size_t)l * DD * HH, bet);

        conv_silu_k<<<eltTD, 256>>>(q, conv_q + (size_t)l * DD * KC, qc);
        conv_silu_k<<<eltTD, 256>>>(k, conv_k + (size_t)l * DD * KC, kc);
        conv_silu_k<<<eltTD, 256>>>(v, conv_v + (size_t)l * DD * KC, vc);

        l2norm_k<<<eltTH, 256>>>(qc);
        l2norm_k<<<eltTH, 256>>>(kc);

        delta_k<<<HH, DKK>>>(qc, kc, vc, bet, o);
        headnorm_k<<<eltTH, 256>>>(o, o_norm_w + (size_t)l * DKK);

        gemm_tc<true><<<g_one, 256>>>(o, Wo + (size_t)l * DD * DD, nullptr, nullptr,
                                      h, nullptr, nullptr, TT, DD, DD);

        rmsnorm_k<<<TT, 256>>>(h, mlp_norm_w + (size_t)l * DD, x);
        gemm_tc<false><<<g_gu, 256>>>(x,
            Wgate + (size_t)l * DD * FFD, Wup + (size_t)l * DD * FFD, nullptr,
            gate, up, nullptr, TT, FFD, DD);
        silu_mul_k<<<eltTF, 256>>>(gate, up);
        gemm_tc<true><<<g_one, 256>>>(gate, Wdown + (size_t)l * FFD * DD, nullptr, nullptr,
                                      h, nullptr, nullptr, TT, DD, FFD);
    }

    rmsnorm_k<<<TT, 256>>>(h, final_norm_w, x);

    if ((long long)out_size >= (long long)TT * VV) {
        gemm_tc<false><<<g_vcb, 256>>>(x, lm_head, nullptr, nullptr,
                                       out, nullptr, nullptr, TT, VV, DD);
        loss_rows_k<<<TT, 256>>>(out, targets, rowloss);
        if ((long long)out_size > (long long)TT * VV)
            loss_final_k<<<1, 256>>>(rowloss, out + (size_t)TT * VV);
    }
}